// round 15
// baseline (speedup 1.0000x reference)
#include <cuda_runtime.h>
#include <cuda_fp16.h>
#include <mma.h>
#include <math.h>
#include <cstdint>

using namespace nvcuda;

#define BB 64
#define TT 512
#define HH 1024
#define BT (BB*TT)
#define NF 128
#define N3H (3*HH)
#define NCHUNK 128
#define GRID 148
#define NTHR 512
#define SEGLEN 32     // scan segment length (16 segments x 64 lanes, 2 blocks)

// ---------------- device scratch (no allocations allowed) ----------------
__device__ float g_part_sum[NCHUNK][HH];
__device__ float g_part_sq[NCHUNK][HH];
__device__ float g_a[HH];
__device__ float g_C;
__device__ float g_WpL1;
__device__ unsigned g_pxmax_u;
__device__ unsigned g_stats_done = 0;
__device__ float g_pxT[TT][BB];     // px transposed [t][b]
__device__ float g_phi[NF][HH];
__device__ float g_gip[2][NF][N3H]; // 2-way K-split GEMM partials
__device__ float g_Ftab[NF];

// ---------------- grid-wide barrier (148 CTAs, 1/SM) ----------------
__device__ unsigned g_bar_count = 0;
__device__ volatile unsigned g_bar_gen = 0;

__device__ __forceinline__ void grid_sync() {
    __syncthreads();
    if (threadIdx.x == 0) {
        __threadfence();
        unsigned gen = g_bar_gen;
        if (atomicAdd(&g_bar_count, 1u) == GRID - 1) {
            g_bar_count = 0;
            __threadfence();
            g_bar_gen = gen + 1;
        } else {
            while (g_bar_gen == gen) { }
        }
        __threadfence();
    }
    __syncthreads();
}

__device__ __forceinline__ void half_bar(int id) {
    asm volatile("bar.sync %0, 256;" :: "r"(id) : "memory");
}

__device__ __forceinline__ float load_R() {
    float wl = __ldcg(&g_WpL1);
    float pxmax = __uint_as_float(__ldcg((const unsigned*)&g_pxmax_u));
    return 0.5f * (pxmax + wl) * 1.02f + 0.25f;
}

__device__ __forceinline__ uint32_t smem_u32(const void* p) {
    uint32_t a;
    asm("{ .reg .u64 t; cvta.to.shared.u64 t, %1; cvt.u32.u64 %0, t; }" : "=r"(a) : "l"(p));
    return a;
}

// ======== pass 1: BN partial sums (512 blocks x 512 thr: ~3.4 CTA/SM) ========
// grid (4, 128): y = 256-row chunk, x = channel quarter (256 ch = 64 float4)
__global__ void __launch_bounds__(512) k_stats(
    const float* __restrict__ x,
    const float* __restrict__ gamma, const float* __restrict__ beta,
    const float* __restrict__ Wp, const float* __restrict__ bp)
{
    __shared__ __align__(16) float4 ss[512], sq[512];
    int t = threadIdx.x;
    int c4 = t & 63;          // float4 index within quarter
    int rsub = t >> 6;        // 0..7: row subgroup (32 rows each)
    {
        const float4* p = (const float4*)(x + (size_t)blockIdx.y * 256 * HH)
                          + (size_t)rsub * 256 + blockIdx.x * 64 + c4;
        float4 s = make_float4(0.f, 0.f, 0.f, 0.f);
        float4 q = make_float4(0.f, 0.f, 0.f, 0.f);
#pragma unroll 16
        for (int r = 0; r < 32; r++) {        // 256 rows / 8 subgroups
            float4 v = *p; p += 8 * 256;
            s.x += v.x; s.y += v.y; s.z += v.z; s.w += v.w;
            q.x += v.x*v.x; q.y += v.y*v.y; q.z += v.z*v.z; q.w += v.w*v.w;
        }
        ss[t] = s; sq[t] = q;
    }
    __syncthreads();
    if (t < 64) {
        float4 s = make_float4(0.f, 0.f, 0.f, 0.f);
        float4 q = make_float4(0.f, 0.f, 0.f, 0.f);
#pragma unroll
        for (int g = 0; g < 8; g++) {
            float4 a0 = ss[t + g * 64], b0 = sq[t + g * 64];
            s.x += a0.x; s.y += a0.y; s.z += a0.z; s.w += a0.w;
            q.x += b0.x; q.y += b0.y; q.z += b0.z; q.w += b0.w;
        }
        ((float4*)g_part_sum[blockIdx.y])[blockIdx.x * 64 + t] = s;
        ((float4*)g_part_sq[blockIdx.y])[blockIdx.x * 64 + t]  = q;
    }
    // -------- last block finalizes (identical math whichever block it is) --------
    __threadfence();
    __shared__ unsigned s_last;
    __syncthreads();
    if (t == 0) s_last = atomicAdd(&g_stats_done, 1u);
    __syncthreads();
    if (s_last != 511u) return;
    if (t == 0) g_stats_done = 0u;            // reset for next graph replay

    float cj_loc = 0.f, aw_loc = 0.f;
    if (t < 256) {                            // one float4 (4 channels) per thread
        float4 s = make_float4(0.f, 0.f, 0.f, 0.f);
        float4 q = make_float4(0.f, 0.f, 0.f, 0.f);
#pragma unroll 8
        for (int c = 0; c < NCHUNK; c++) {
            float4 vs = __ldcg(&((const float4*)g_part_sum[c])[t]);
            float4 vq = __ldcg(&((const float4*)g_part_sq[c])[t]);
            s.x += vs.x; s.y += vs.y; s.z += vs.z; s.w += vs.w;
            q.x += vq.x; q.y += vq.y; q.z += vq.z; q.w += vq.w;
        }
        float4 gm = __ldg(&((const float4*)gamma)[t]);
        float4 bt = __ldg(&((const float4*)beta)[t]);
        float4 wp = __ldg(&((const float4*)Wp)[t]);
        float sa[4] = {s.x, s.y, s.z, s.w}, qa[4] = {q.x, q.y, q.z, q.w};
        float ga[4] = {gm.x, gm.y, gm.z, gm.w}, ba[4] = {bt.x, bt.y, bt.z, bt.w};
        float wa[4] = {wp.x, wp.y, wp.z, wp.w};
        float aa[4], ca[4];
#pragma unroll
        for (int i = 0; i < 4; i++) {
            float mean = sa[i] * (1.0f / BT);
            float var  = qa[i] * (1.0f / BT) - mean * mean;
            float rstd = rsqrtf(var + 1e-5f);
            aa[i] = ga[i] * rstd * wa[i];
            ca[i] = (ba[i] - mean * rstd * ga[i]) * wa[i];
        }
        ((float4*)g_a)[t] = make_float4(aa[0], aa[1], aa[2], aa[3]);
        cj_loc = (ca[0] + ca[1]) + (ca[2] + ca[3]);
        aw_loc = (fabsf(wa[0]) + fabsf(wa[1])) + (fabsf(wa[2]) + fabsf(wa[3]));
    }
    float* sc = (float*)ss;
    float* sw = (float*)sq;
    sc[t] = cj_loc; sw[t] = aw_loc;           // zeros for t >= 256
    __syncthreads();
    for (int st = 256; st > 0; st >>= 1) {
        if (t < st) { sc[t] += sc[t + st]; sw[t] += sw[t + st]; }
        __syncthreads();
    }
    if (t == 0) {
        g_C = sc[0] + bp[0];
        g_WpL1 = sw[0] + fabsf(bp[0]);
        g_pxmax_u = 0u;
    }
}

// ===== pass 2: px (row chunks REVERSED: tail of x is L2-hot after k_stats) =====
__global__ void k_px(const float* __restrict__ x) {
    int w = threadIdx.x >> 5, lane = threadIdx.x & 31;
    int r = (gridDim.x - 1 - blockIdx.x) * 8 + w;   // descending chunk order
    const float4* xr = (const float4*)(x + (size_t)r * HH);
    const float4* a4 = (const float4*)g_a;
    float acc = 0.f;
#pragma unroll
    for (int i = 0; i < 8; i++) {
        float4 xv = xr[lane + i * 32];
        float4 av = __ldg(&a4[lane + i * 32]);
        acc += xv.x * av.x + xv.y * av.y + xv.z * av.z + xv.w * av.w;
    }
#pragma unroll
    for (int off = 16; off; off >>= 1) acc += __shfl_down_sync(0xFFFFFFFFu, acc, off);
    __shared__ float wm[8];
    if (lane == 0) {
        float v = acc + g_C;
        g_pxT[r & (TT - 1)][r >> 9] = v;
        wm[w] = fabsf(v);
    }
    __syncthreads();
    if (threadIdx.x == 0) {
        float m = wm[0];
#pragma unroll
        for (int i = 1; i < 8; i++) m = fmaxf(m, wm[i]);
        atomicMax(&g_pxmax_u, __float_as_uint(m));
    }
}

// ========== fused: phi -> fp16 WMMA GEMM -> tail -> segmented scan ==========
#define LDMH 72

__global__ void __launch_bounds__(NTHR, 1) k_table(
    const float* __restrict__ W0, const float* __restrict__ bih0,
    const float* __restrict__ bhh0,
    const float* __restrict__ W1, const float* __restrict__ bih1,
    const float* __restrict__ bhh1,
    const float* __restrict__ Wp, const float* __restrict__ bp,
    float* __restrict__ out)
{
    __shared__ __align__(16) char s_mem[36992];
    float* s_buf = (float*)s_mem;
    int b = blockIdx.x, tid = threadIdx.x;

    // ---- phase A: phi table (layer-0 GRU cell, h=0) ----
    {
        float R = load_R();
        float s0v = -R, delta = 2.f * R / (float)(NF - 1);
        for (int idx = b * NTHR + tid; idx < NF * HH; idx += GRID * NTHR) {
            int i = idx >> 10, j = idx & (HH - 1);
            float s = s0v + (float)i * delta;
            float ar = fmaf(s, W0[j],          bih0[j]        + bhh0[j]);
            float az = fmaf(s, W0[HH + j],     bih0[HH + j]   + bhh0[HH + j]);
            float r = 1.f / (1.f + expf(-ar));
            float z = 1.f / (1.f + expf(-az));
            float an = fmaf(s, W0[2*HH + j], fmaf(r, bhh0[2*HH + j], bih0[2*HH + j]));
            g_phi[i][j] = (1.f - z) * tanhf(an);
        }
    }
    grid_sync();

    // ---- phase B: fp16 WMMA GEMM, 192 jobs 64x64xK512, register double-buffer ----
    {
        int half = tid >> 8;
        int ltid = tid & 255;
        int job = b + half * GRID;
        if (job < 192) {
            __half (*As)[LDMH] = (__half(*)[LDMH])(s_mem + half * 18496);
            __half (*Bs)[LDMH] = (__half(*)[LDMH])(s_mem + half * 18496 + 9248);
            int kseg = job / 96, rem = job % 96;
            int m0 = (rem & 1) * 64, n0 = (rem >> 1) * 64;
            int w = ltid >> 5;
            int wm = w >> 1, wn = w & 1;
            int sr = ltid >> 2;
            int sc = (ltid & 3) * 16;

            wmma::fragment<wmma::accumulator, 16, 16, 16, float> acc[2];
            wmma::fill_fragment(acc[0], 0.0f);
            wmma::fill_fragment(acc[1], 0.0f);

            float4 ra[4], rb[4];
            {
                int k0 = kseg * 512;
                const float4* pa = (const float4*)&g_phi[m0 + sr][k0] + (sc >> 2);
                const float4* pb = (const float4*)&W1[(size_t)(n0 + sr) * HH + k0] + (sc >> 2);
#pragma unroll
                for (int j = 0; j < 4; j++) { ra[j] = pa[j]; rb[j] = pb[j]; }
            }
            for (int kc = 0; kc < 8; kc++) {
                half_bar(half + 1);
#pragma unroll
                for (int j = 0; j < 4; j++) {
                    union { __half2 h[2]; uint2 u; } t;
                    t.h[0] = __floats2half2_rn(ra[j].x, ra[j].y);
                    t.h[1] = __floats2half2_rn(ra[j].z, ra[j].w);
                    *(uint2*)&As[sr][sc + j * 4] = t.u;
                    t.h[0] = __floats2half2_rn(rb[j].x, rb[j].y);
                    t.h[1] = __floats2half2_rn(rb[j].z, rb[j].w);
                    *(uint2*)&Bs[sr][sc + j * 4] = t.u;
                }
                half_bar(half + 1);
                if (kc < 7) {
                    int k0 = kseg * 512 + (kc + 1) * 64;
                    const float4* pa = (const float4*)&g_phi[m0 + sr][k0] + (sc >> 2);
                    const float4* pb = (const float4*)&W1[(size_t)(n0 + sr) * HH + k0] + (sc >> 2);
#pragma unroll
                    for (int j = 0; j < 4; j++) { ra[j] = pa[j]; rb[j] = pb[j]; }
                }
#pragma unroll
                for (int ks = 0; ks < 4; ks++) {
                    int kk = ks * 16;
                    wmma::fragment<wmma::matrix_a, 16, 16, 16, __half, wmma::row_major> fa;
                    wmma::fragment<wmma::matrix_b, 16, 16, 16, __half, wmma::col_major> fb0, fb1;
                    wmma::load_matrix_sync(fa,  &As[wm * 16][kk], LDMH);
                    wmma::load_matrix_sync(fb0, &Bs[wn * 32][kk], LDMH);
                    wmma::load_matrix_sync(fb1, &Bs[wn * 32 + 16][kk], LDMH);
                    wmma::mma_sync(acc[0], fa, fb0, acc[0]);
                    wmma::mma_sync(acc[1], fa, fb1, acc[1]);
                }
            }
            wmma::store_matrix_sync(&g_gip[kseg][m0 + wm * 16][n0 + wn * 32],
                                    acc[0], N3H, wmma::mem_row_major);
            wmma::store_matrix_sync(&g_gip[kseg][m0 + wm * 16][n0 + wn * 32 + 16],
                                    acc[1], N3H, wmma::mem_row_major);
        }
    }
    grid_sync();

    // ---- phase C: sum K-partials + layer-1 nonlin + projection (blocks 0..127) ----
    if (b < NF) {
        float acc = 0.f;
        for (int ch = tid; ch < HH; ch += NTHR) {
            float gr = (__ldcg(&g_gip[0][b][ch])        + __ldcg(&g_gip[1][b][ch]))        + bih1[ch];
            float gz = (__ldcg(&g_gip[0][b][HH + ch])   + __ldcg(&g_gip[1][b][HH + ch]))   + bih1[HH + ch];
            float gn = (__ldcg(&g_gip[0][b][2*HH + ch]) + __ldcg(&g_gip[1][b][2*HH + ch])) + bih1[2*HH + ch];
            float r = 1.f / (1.f + expf(-(gr + bhh1[ch])));
            float z = 1.f / (1.f + expf(-(gz + bhh1[HH + ch])));
            float n = tanhf(gn + r * bhh1[2*HH + ch]);
            acc += Wp[ch] * (1.f - z) * n;
        }
        s_buf[tid] = acc;
        __syncthreads();
        for (int st = 256; st > 0; st >>= 1) {
            if (tid < st) s_buf[tid] += s_buf[tid + st];
            __syncthreads();
        }
        if (tid == 0) g_Ftab[b] = s_buf[0] + bp[0];
    }
    grid_sync();

    // ---- phase D: segmented scan, blocks 0-1: 16 segments x 64 lanes ----
    // Segments >0 start f=0 and warm up 32 steps; contraction |F'|/2 (~0.25
    // empirically) kills the init error by rho^32 << 1e-9.
    if (b < 2) {
        float4* tab = (float4*)s_buf;   // per-cell monomial coeffs {c0,c1,c2,c3}
        for (int i = tid; i < NF; i += NTHR) {
            float a = __ldcg(&g_Ftab[i > 0 ? i - 1 : 0]);
            float bb = __ldcg(&g_Ftab[i]);
            float c = __ldcg(&g_Ftab[i < NF - 1 ? i + 1 : NF - 1]);
            float d = __ldcg(&g_Ftab[i < NF - 2 ? i + 2 : NF - 1]);
            float c0 = (-a + 9.f*bb + 9.f*c - d) * (1.f/16.f);
            float c1 = (a - d) * (1.f/24.f) + (c - bb) * (9.f/8.f);
            float c2 = (a - bb - c + d) * 0.25f;
            float c3 = (-a + 3.f*bb - 3.f*c + d) * (1.f/6.f);
            tab[i] = make_float4(c0, c1, c2, c3);
        }
        float R = load_R();
        float invd = (float)(NF - 1) / (2.f * R);
        float k1 = 0.5f * invd;
        float base = R * invd - 0.5f;          // -0.5: round(u) == floor(true_u)
        __syncthreads();
        const float MAGIC = 12582912.0f;       // 2^23 + 2^22, bits 0x4B400000
        uint32_t adj = smem_u32(tab) - (0x4B400000u << 4);

        int seg = b * 8 + (tid >> 6);          // 0..15 (warp-uniform)
        int lane = tid & 63;                   // batch index
        int nwarm = (seg == 0) ? 0 : SEGLEN;
        int t0base = seg * SEGLEN - nwarm;
        int ntot = nwarm + SEGLEN;             // 32 or 64, multiple of 8
        float* o = out + lane * TT;
        float f = 0.f;
        float buf[8];
#pragma unroll
        for (int i = 0; i < 8; i++) buf[i] = __ldcg(&g_pxT[t0base + i][lane]);
        for (int tb = 0; tb < ntot; tb += 8) {
#pragma unroll
            for (int i = 0; i < 8; i++) {
                float pxv = buf[i];
                int rel = tb + 8 + i;
                if (rel < ntot) buf[i] = __ldcg(&g_pxT[t0base + rel][lane]);
                float pb = fmaf(pxv, k1, base);
                float u = fmaf(f, k1, pb);
                float fm = u + MAGIC;
                uint32_t addr = __float_as_uint(fm) * 16u + adj;
                float4 P;
                asm volatile("ld.shared.v4.f32 {%0,%1,%2,%3}, [%4];"
                             : "=f"(P.x), "=f"(P.y), "=f"(P.z), "=f"(P.w) : "r"(addr));
                float y = u - (fm - MAGIC);
                float q = y * y;
                float A  = fmaf(P.y, y, P.x);
                float Bv = fmaf(P.w, y, P.z);
                f = fmaf(q, Bv, A);
                int step = tb + i;
                if (step >= nwarm) o[t0base + step] = f;
            }
        }
    }
}

extern "C" void kernel_launch(void* const* d_in, const int* in_sizes, int n_in,
                              void* d_out, int out_size) {
    const float* x     = (const float*)d_in[0];
    // d_in[1] timestamp: unused
    const float* gamma = (const float*)d_in[2];
    const float* beta  = (const float*)d_in[3];
    const float* Wih0  = (const float*)d_in[4];
    const float* bih0  = (const float*)d_in[5];
    // d_in[6] W_hh0 unused (h_prev = 0)
    const float* bhh0  = (const float*)d_in[7];
    const float* Wih1  = (const float*)d_in[8];
    const float* bih1  = (const float*)d_in[9];
    // d_in[10] W_hh1 unused
    const float* bhh1  = (const float*)d_in[11];
    const float* Wp    = (const float*)d_in[12];
    const float* bp    = (const float*)d_in[13];
    float* out = (float*)d_out;

    k_stats<<<dim3(4, 128), 512>>>(x, gamma, beta, Wp, bp);
    k_px<<<BT / 8, 256>>>(x);
    k_table<<<GRID, NTHR>>>(Wih0, bih0, bhh0, Wih1, bih1, bhh1, Wp, bp, out);
}

// round 16
// speedup vs baseline: 1.1172x; 1.1172x over previous
#include <cuda_runtime.h>
#include <cuda_fp16.h>
#include <mma.h>
#include <math.h>
#include <cstdint>

using namespace nvcuda;

#define BB 64
#define TT 512
#define HH 1024
#define BT (BB*TT)
#define NF 128
#define N3H (3*HH)
#define NCHUNK 64
#define GRID 148
#define NTHR 512
#define SEGLEN 32     // scan segment length (16 segments x 64 lanes, 2 blocks)

// ---------------- device scratch (no allocations allowed) ----------------
__device__ float g_part_sum[NCHUNK][HH];
__device__ float g_part_sq[NCHUNK][HH];
__device__ float g_a[HH];
__device__ float g_C;
__device__ float g_WpL1;
__device__ unsigned g_pxmax_u;
__device__ unsigned g_stats_done = 0;
__device__ float g_pxT[TT][BB];     // px transposed [t][b]
__device__ float g_phi[NF][HH];
__device__ float g_gip[4][NF][N3H]; // 4-way K-split GEMM partials
__device__ float g_Ftab[NF];

// ---------------- grid-wide barrier (148 CTAs, 1/SM) ----------------
__device__ unsigned g_bar_count = 0;
__device__ volatile unsigned g_bar_gen = 0;

__device__ __forceinline__ void grid_sync() {
    __syncthreads();
    if (threadIdx.x == 0) {
        __threadfence();
        unsigned gen = g_bar_gen;
        if (atomicAdd(&g_bar_count, 1u) == GRID - 1) {
            g_bar_count = 0;
            __threadfence();
            g_bar_gen = gen + 1;
        } else {
            while (g_bar_gen == gen) { }
        }
        __threadfence();
    }
    __syncthreads();
}

__device__ __forceinline__ void half_bar(int id) {
    asm volatile("bar.sync %0, 256;" :: "r"(id) : "memory");
}

__device__ __forceinline__ float load_R() {
    float wl = __ldcg(&g_WpL1);
    float pxmax = __uint_as_float(__ldcg((const unsigned*)&g_pxmax_u));
    return 0.5f * (pxmax + wl) * 1.02f + 0.25f;
}

__device__ __forceinline__ uint32_t smem_u32(const void* p) {
    uint32_t a;
    asm("{ .reg .u64 t; cvta.to.shared.u64 t, %1; cvt.u32.u64 %0, t; }" : "=r"(a) : "l"(p));
    return a;
}

// ======== pass 1: BN partial sums (R14-proven: 256 blocks x 512 thr) ========
// grid (4, 64): y = 512-row chunk, x = channel quarter (256 ch = 64 float4)
__global__ void __launch_bounds__(512) k_stats(
    const float* __restrict__ x,
    const float* __restrict__ gamma, const float* __restrict__ beta,
    const float* __restrict__ Wp, const float* __restrict__ bp)
{
    __shared__ __align__(16) float4 ss[512], sq[512];
    int t = threadIdx.x;
    int c4 = t & 63;          // float4 index within quarter
    int rsub = t >> 6;        // 0..7: row subgroup (64 rows each)
    {
        const float4* p = (const float4*)(x + (size_t)blockIdx.y * 512 * HH)
                          + (size_t)rsub * 256 + blockIdx.x * 64 + c4;
        float4 s = make_float4(0.f, 0.f, 0.f, 0.f);
        float4 q = make_float4(0.f, 0.f, 0.f, 0.f);
#pragma unroll 8
        for (int r = 0; r < 64; r++) {        // 512 rows / 8 subgroups
            float4 v = *p; p += 8 * 256;
            s.x += v.x; s.y += v.y; s.z += v.z; s.w += v.w;
            q.x += v.x*v.x; q.y += v.y*v.y; q.z += v.z*v.z; q.w += v.w*v.w;
        }
        ss[t] = s; sq[t] = q;
    }
    __syncthreads();
    if (t < 64) {
        float4 s = make_float4(0.f, 0.f, 0.f, 0.f);
        float4 q = make_float4(0.f, 0.f, 0.f, 0.f);
#pragma unroll
        for (int g = 0; g < 8; g++) {
            float4 a0 = ss[t + g * 64], b0 = sq[t + g * 64];
            s.x += a0.x; s.y += a0.y; s.z += a0.z; s.w += a0.w;
            q.x += b0.x; q.y += b0.y; q.z += b0.z; q.w += b0.w;
        }
        ((float4*)g_part_sum[blockIdx.y])[blockIdx.x * 64 + t] = s;
        ((float4*)g_part_sq[blockIdx.y])[blockIdx.x * 64 + t]  = q;
    }
    // -------- last block finalizes (identical math whichever block it is) --------
    __threadfence();
    __shared__ unsigned s_last;
    __syncthreads();
    if (t == 0) s_last = atomicAdd(&g_stats_done, 1u);
    __syncthreads();
    if (s_last != 255u) return;
    if (t == 0) g_stats_done = 0u;            // reset for next graph replay

    float cj_loc = 0.f, aw_loc = 0.f;
    if (t < 256) {                            // one float4 (4 channels) per thread
        float4 s = make_float4(0.f, 0.f, 0.f, 0.f);
        float4 q = make_float4(0.f, 0.f, 0.f, 0.f);
#pragma unroll 8
        for (int c = 0; c < NCHUNK; c++) {
            float4 vs = __ldcg(&((const float4*)g_part_sum[c])[t]);
            float4 vq = __ldcg(&((const float4*)g_part_sq[c])[t]);
            s.x += vs.x; s.y += vs.y; s.z += vs.z; s.w += vs.w;
            q.x += vq.x; q.y += vq.y; q.z += vq.z; q.w += vq.w;
        }
        float4 gm = __ldg(&((const float4*)gamma)[t]);
        float4 bt = __ldg(&((const float4*)beta)[t]);
        float4 wp = __ldg(&((const float4*)Wp)[t]);
        float sa[4] = {s.x, s.y, s.z, s.w}, qa[4] = {q.x, q.y, q.z, q.w};
        float ga[4] = {gm.x, gm.y, gm.z, gm.w}, ba[4] = {bt.x, bt.y, bt.z, bt.w};
        float wa[4] = {wp.x, wp.y, wp.z, wp.w};
        float aa[4], ca[4];
#pragma unroll
        for (int i = 0; i < 4; i++) {
            float mean = sa[i] * (1.0f / BT);
            float var  = qa[i] * (1.0f / BT) - mean * mean;
            float rstd = rsqrtf(var + 1e-5f);
            aa[i] = ga[i] * rstd * wa[i];
            ca[i] = (ba[i] - mean * rstd * ga[i]) * wa[i];
        }
        ((float4*)g_a)[t] = make_float4(aa[0], aa[1], aa[2], aa[3]);
        cj_loc = (ca[0] + ca[1]) + (ca[2] + ca[3]);
        aw_loc = (fabsf(wa[0]) + fabsf(wa[1])) + (fabsf(wa[2]) + fabsf(wa[3]));
    }
    float* sc = (float*)ss;
    float* sw = (float*)sq;
    sc[t] = cj_loc; sw[t] = aw_loc;           // zeros for t >= 256
    __syncthreads();
    for (int st = 256; st > 0; st >>= 1) {
        if (t < st) { sc[t] += sc[t + st]; sw[t] += sw[t + st]; }
        __syncthreads();
    }
    if (t == 0) {
        g_C = sc[0] + bp[0];
        g_WpL1 = sw[0] + fabsf(bp[0]);
        g_pxmax_u = 0u;
    }
}

// ===== pass 2: px (row chunks REVERSED: tail of x is L2-hot after k_stats) =====
__global__ void k_px(const float* __restrict__ x) {
    int w = threadIdx.x >> 5, lane = threadIdx.x & 31;
    int r = (gridDim.x - 1 - blockIdx.x) * 8 + w;   // descending chunk order
    const float4* xr = (const float4*)(x + (size_t)r * HH);
    const float4* a4 = (const float4*)g_a;
    float acc = 0.f;
#pragma unroll
    for (int i = 0; i < 8; i++) {
        float4 xv = xr[lane + i * 32];
        float4 av = __ldg(&a4[lane + i * 32]);
        acc += xv.x * av.x + xv.y * av.y + xv.z * av.z + xv.w * av.w;
    }
#pragma unroll
    for (int off = 16; off; off >>= 1) acc += __shfl_down_sync(0xFFFFFFFFu, acc, off);
    __shared__ float wm[8];
    if (lane == 0) {
        float v = acc + g_C;
        g_pxT[r & (TT - 1)][r >> 9] = v;
        wm[w] = fabsf(v);
    }
    __syncthreads();
    if (threadIdx.x == 0) {
        float m = wm[0];
#pragma unroll
        for (int i = 1; i < 8; i++) m = fmaxf(m, wm[i]);
        atomicMax(&g_pxmax_u, __float_as_uint(m));
    }
}

// ========== fused: phi -> fp16 WMMA GEMM -> tail -> segmented scan ==========
#define LDMH 72

__global__ void __launch_bounds__(NTHR, 1) k_table(
    const float* __restrict__ W0, const float* __restrict__ bih0,
    const float* __restrict__ bhh0,
    const float* __restrict__ W1, const float* __restrict__ bih1,
    const float* __restrict__ bhh1,
    const float* __restrict__ Wp, const float* __restrict__ bp,
    float* __restrict__ out)
{
    __shared__ __align__(16) char s_mem[36992];
    float* s_buf = (float*)s_mem;
    int b = blockIdx.x, tid = threadIdx.x;

    // ---- phase A: phi table (layer-0 GRU cell, h=0) ----
    {
        float R = load_R();
        float s0v = -R, delta = 2.f * R / (float)(NF - 1);
        for (int idx = b * NTHR + tid; idx < NF * HH; idx += GRID * NTHR) {
            int i = idx >> 10, j = idx & (HH - 1);
            float s = s0v + (float)i * delta;
            float ar = fmaf(s, W0[j],          bih0[j]        + bhh0[j]);
            float az = fmaf(s, W0[HH + j],     bih0[HH + j]   + bhh0[HH + j]);
            float r = 1.f / (1.f + expf(-ar));
            float z = 1.f / (1.f + expf(-az));
            float an = fmaf(s, W0[2*HH + j], fmaf(r, bhh0[2*HH + j], bih0[2*HH + j]));
            g_phi[i][j] = (1.f - z) * tanhf(an);
        }
    }
    grid_sync();

    // ---- phase B: fp16 WMMA GEMM, 384 jobs 64x64xK256 (4-way K-split) ----
    // Half-blocks process jobs {b + half*148} and {+296}: critical path 2 jobs
    // of 4 chunk-iters each (vs 2x8 with K512 jobs).
    {
        int half = tid >> 8;
        int ltid = tid & 255;
        __half (*As)[LDMH] = (__half(*)[LDMH])(s_mem + half * 18496);
        __half (*Bs)[LDMH] = (__half(*)[LDMH])(s_mem + half * 18496 + 9248);
        int w = ltid >> 5;
        int wm = w >> 1, wn = w & 1;
        int sr = ltid >> 2;
        int sc = (ltid & 3) * 16;
        for (int jj = 0; jj < 2; jj++) {
            int job = b + half * GRID + jj * 2 * GRID;   // b+half*148 (+296)
            if (job >= 384) break;
            int kseg = job / 96, rem = job % 96;
            int m0 = (rem & 1) * 64, n0 = (rem >> 1) * 64;

            wmma::fragment<wmma::accumulator, 16, 16, 16, float> acc[2];
            wmma::fill_fragment(acc[0], 0.0f);
            wmma::fill_fragment(acc[1], 0.0f);

            float4 ra[4], rb[4];
            {
                int k0 = kseg * 256;
                const float4* pa = (const float4*)&g_phi[m0 + sr][k0] + (sc >> 2);
                const float4* pb = (const float4*)&W1[(size_t)(n0 + sr) * HH + k0] + (sc >> 2);
#pragma unroll
                for (int j = 0; j < 4; j++) { ra[j] = pa[j]; rb[j] = pb[j]; }
            }
            for (int kc = 0; kc < 4; kc++) {             // 4 chunks of 64 K
                half_bar(half + 1);                      // prior readers done
#pragma unroll
                for (int j = 0; j < 4; j++) {
                    union { __half2 h[2]; uint2 u; } t;
                    t.h[0] = __floats2half2_rn(ra[j].x, ra[j].y);
                    t.h[1] = __floats2half2_rn(ra[j].z, ra[j].w);
                    *(uint2*)&As[sr][sc + j * 4] = t.u;
                    t.h[0] = __floats2half2_rn(rb[j].x, rb[j].y);
                    t.h[1] = __floats2half2_rn(rb[j].z, rb[j].w);
                    *(uint2*)&Bs[sr][sc + j * 4] = t.u;
                }
                half_bar(half + 1);                      // tiles staged
                if (kc < 3) {                            // prefetch next chunk
                    int k0 = kseg * 256 + (kc + 1) * 64;
                    const float4* pa = (const float4*)&g_phi[m0 + sr][k0] + (sc >> 2);
                    const float4* pb = (const float4*)&W1[(size_t)(n0 + sr) * HH + k0] + (sc >> 2);
#pragma unroll
                    for (int j = 0; j < 4; j++) { ra[j] = pa[j]; rb[j] = pb[j]; }
                }
#pragma unroll
                for (int ks = 0; ks < 4; ks++) {
                    int kk = ks * 16;
                    wmma::fragment<wmma::matrix_a, 16, 16, 16, __half, wmma::row_major> fa;
                    wmma::fragment<wmma::matrix_b, 16, 16, 16, __half, wmma::col_major> fb0, fb1;
                    wmma::load_matrix_sync(fa,  &As[wm * 16][kk], LDMH);
                    wmma::load_matrix_sync(fb0, &Bs[wn * 32][kk], LDMH);
                    wmma::load_matrix_sync(fb1, &Bs[wn * 32 + 16][kk], LDMH);
                    wmma::mma_sync(acc[0], fa, fb0, acc[0]);
                    wmma::mma_sync(acc[1], fa, fb1, acc[1]);
                }
            }
            wmma::store_matrix_sync(&g_gip[kseg][m0 + wm * 16][n0 + wn * 32],
                                    acc[0], N3H, wmma::mem_row_major);
            wmma::store_matrix_sync(&g_gip[kseg][m0 + wm * 16][n0 + wn * 32 + 16],
                                    acc[1], N3H, wmma::mem_row_major);
        }
    }
    grid_sync();

    // ---- phase C: sum 4 K-partials + layer-1 nonlin + projection (blocks 0..127) ----
    if (b < NF) {
        float acc = 0.f;
        for (int ch = tid; ch < HH; ch += NTHR) {
            float gr = ((__ldcg(&g_gip[0][b][ch])        + __ldcg(&g_gip[1][b][ch])) +
                        (__ldcg(&g_gip[2][b][ch])        + __ldcg(&g_gip[3][b][ch]))) + bih1[ch];
            float gz = ((__ldcg(&g_gip[0][b][HH + ch])   + __ldcg(&g_gip[1][b][HH + ch])) +
                        (__ldcg(&g_gip[2][b][HH + ch])   + __ldcg(&g_gip[3][b][HH + ch]))) + bih1[HH + ch];
            float gn = ((__ldcg(&g_gip[0][b][2*HH + ch]) + __ldcg(&g_gip[1][b][2*HH + ch])) +
                        (__ldcg(&g_gip[2][b][2*HH + ch]) + __ldcg(&g_gip[3][b][2*HH + ch]))) + bih1[2*HH + ch];
            float r = 1.f / (1.f + expf(-(gr + bhh1[ch])));
            float z = 1.f / (1.f + expf(-(gz + bhh1[HH + ch])));
            float n = tanhf(gn + r * bhh1[2*HH + ch]);
            acc += Wp[ch] * (1.f - z) * n;
        }
        s_buf[tid] = acc;
        __syncthreads();
        for (int st = 256; st > 0; st >>= 1) {
            if (tid < st) s_buf[tid] += s_buf[tid + st];
            __syncthreads();
        }
        if (tid == 0) g_Ftab[b] = s_buf[0] + bp[0];
    }
    grid_sync();

    // ---- phase D: segmented scan, blocks 0-1: 16 segments x 64 lanes ----
    // Segments >0 start f=0 and warm up 32 steps; contraction |F'|/2 (~0.25
    // empirically) kills the init error by rho^32 << 1e-9.
    if (b < 2) {
        float4* tab = (float4*)s_buf;   // per-cell monomial coeffs {c0,c1,c2,c3}
        for (int i = tid; i < NF; i += NTHR) {
            float a = __ldcg(&g_Ftab[i > 0 ? i - 1 : 0]);
            float bb = __ldcg(&g_Ftab[i]);
            float c = __ldcg(&g_Ftab[i < NF - 1 ? i + 1 : NF - 1]);
            float d = __ldcg(&g_Ftab[i < NF - 2 ? i + 2 : NF - 1]);
            float c0 = (-a + 9.f*bb + 9.f*c - d) * (1.f/16.f);
            float c1 = (a - d) * (1.f/24.f) + (c - bb) * (9.f/8.f);
            float c2 = (a - bb - c + d) * 0.25f;
            float c3 = (-a + 3.f*bb - 3.f*c + d) * (1.f/6.f);
            tab[i] = make_float4(c0, c1, c2, c3);
        }
        float R = load_R();
        float invd = (float)(NF - 1) / (2.f * R);
        float k1 = 0.5f * invd;
        float base = R * invd - 0.5f;          // -0.5: round(u) == floor(true_u)
        __syncthreads();
        const float MAGIC = 12582912.0f;       // 2^23 + 2^22, bits 0x4B400000
        uint32_t adj = smem_u32(tab) - (0x4B400000u << 4);

        int seg = b * 8 + (tid >> 6);          // 0..15 (warp-uniform)
        int lane = tid & 63;                   // batch index
        int nwarm = (seg == 0) ? 0 : SEGLEN;
        int t0base = seg * SEGLEN - nwarm;
        int ntot = nwarm + SEGLEN;             // 32 or 64, multiple of 8
        float* o = out + lane * TT;
        float f = 0.f;
        float buf[8];
#pragma unroll
        for (int i = 0; i < 8; i++) buf[i] = __ldcg(&g_pxT[t0base + i][lane]);
        for (int tb = 0; tb < ntot; tb += 8) {
#pragma unroll
            for (int i = 0; i < 8; i++) {
                float pxv = buf[i];
                int rel = tb + 8 + i;
                if (rel < ntot) buf[i] = __ldcg(&g_pxT[t0base + rel][lane]);
                float pb = fmaf(pxv, k1, base);
                float u = fmaf(f, k1, pb);
                float fm = u + MAGIC;
                uint32_t addr = __float_as_uint(fm) * 16u + adj;
                float4 P;
                asm volatile("ld.shared.v4.f32 {%0,%1,%2,%3}, [%4];"
                             : "=f"(P.x), "=f"(P.y), "=f"(P.z), "=f"(P.w) : "r"(addr));
                float y = u - (fm - MAGIC);
                float q = y * y;
                float A  = fmaf(P.y, y, P.x);
                float Bv = fmaf(P.w, y, P.z);
                f = fmaf(q, Bv, A);
                int step = tb + i;
                if (step >= nwarm) o[t0base + step] = f;
            }
        }
    }
}

extern "C" void kernel_launch(void* const* d_in, const int* in_sizes, int n_in,
                              void* d_out, int out_size) {
    const float* x     = (const float*)d_in[0];
    // d_in[1] timestamp: unused
    const float* gamma = (const float*)d_in[2];
    const float* beta  = (const float*)d_in[3];
    const float* Wih0  = (const float*)d_in[4];
    const float* bih0  = (const float*)d_in[5];
    // d_in[6] W_hh0 unused (h_prev = 0)
    const float* bhh0  = (const float*)d_in[7];
    const float* Wih1  = (const float*)d_in[8];
    const float* bih1  = (const float*)d_in[9];
    // d_in[10] W_hh1 unused
    const float* bhh1  = (const float*)d_in[11];
    const float* Wp    = (const float*)d_in[12];
    const float* bp    = (const float*)d_in[13];
    float* out = (float*)d_out;

    k_stats<<<dim3(4, 64), 512>>>(x, gamma, beta, Wp, bp);
    k_px<<<BT / 8, 256>>>(x);
    k_table<<<GRID, NTHR>>>(Wih0, bih0, bhh0, Wih1, bih1, bhh1, Wp, bp, out);
}